// round 9
// baseline (speedup 1.0000x reference)
#include <cuda_runtime.h>
#include <cuda_fp16.h>
#include <cstdint>

// out[b,k] = sum_ij in1[b,i]*in2[b,j]*cb[k,ij]   (GEMM: out = P @ Bmat)
// mma.sync.m16n8k16 f16, exact 2-mma product per 8x8 block:
//   mma1: [ph|pl] x [bh|bh], mma2: [ph|pl] x [bl|bl]  => exact p*b.
// Runtime 8x8 block-sparsity, BRANCH-FREE: every (kt,nt) block is a
// uniform-predicated asm body (@p LDS.64 + @p mma + @q mma) — no BSSY/BSYNC
// regions (C++ if{} creates 121 of them; the round-5/8 stall source).
// lo-skip: blocks exactly representable in fp16 (bl==0) predicate off mma2.

#define NKOUT 81
#define NIJ   81
#define NT    11
#define KT    11
#define NBLK  (NT * KT)
#define TPB   256
#define ROWS  128

__device__ uint2    g_blk[NBLK * 32];
__device__ unsigned g_mask[KT];     // bit nt: block (kt,nt) has any nonzero
__device__ unsigned g_lomask[KT];   // bit nt: block needs the lo (bl) mma
__device__ int      g_nslot;

__global__ void prep_kernel(const float* __restrict__ cb) {
    __shared__ int      flag[NBLK];
    __shared__ int      slotof[NBLK];
    __shared__ unsigned smask[KT];
    __shared__ unsigned slomask[KT];
    const int tid = threadIdx.x;
    if (tid < KT) { smask[tid] = 0; slomask[tid] = 0; }
    __syncthreads();

    const int kt = tid / NT;
    const int nt = tid % NT;
    if (tid < NBLK) {
        int f = 0, fl = 0;
        for (int q = 0; q < 8; q++)
            for (int n = 0; n < 8; n++) {
                int ij = kt * 8 + q, ko = nt * 8 + n;
                float v = (ij < NIJ && ko < NKOUT) ? cb[ko * NIJ + ij] : 0.f;
                if (v != 0.f) f = 1;
                float r = v - __half2float(__float2half_rn(v));
                if (r != 0.f) fl = 1;
            }
        flag[tid] = f;
        if (f) atomicOr(&smask[kt], 1u << nt);
        if (f && fl) atomicOr(&slomask[kt], 1u << nt);
    }
    __syncthreads();
    if (tid == 0) {
        int s = 0;
        for (int b = 0; b < NBLK; b++) { slotof[b] = s; s += flag[b]; }
        g_nslot = s;
    }
    __syncthreads();
    if (tid < KT) { g_mask[tid] = smask[tid]; g_lomask[tid] = slomask[tid]; }

    if (tid < NBLK && flag[tid]) {
        const int slot = slotof[tid];
        for (int L = 0; L < 32; L++) {
            int g = L >> 2, t = L & 3;        // b frag: {B[2t][g], B[2t+1][g]}
            int ko  = nt * 8 + g;
            int ij0 = kt * 8 + 2 * t, ij1 = ij0 + 1;
            float v0 = (ij0 < NIJ && ko < NKOUT) ? cb[ko * NIJ + ij0] : 0.f;
            float v1 = (ij1 < NIJ && ko < NKOUT) ? cb[ko * NIJ + ij1] : 0.f;
            __half h0 = __float2half_rn(v0);
            __half h1 = __float2half_rn(v1);
            __half2 bh = __halves2half2(h0, h1);
            __half2 bl = __halves2half2(__float2half_rn(v0 - __half2float(h0)),
                                        __float2half_rn(v1 - __half2float(h1)));
            uint2 u;
            u.x = *(unsigned*)&bh;
            u.y = *(unsigned*)&bl;
            g_blk[slot * 32 + L] = u;
        }
    }
}

// Branch-free predicated block body: if act, load B frag + hi mma; if lo, lo mma.
// Predicates are warp-uniform (derived from shared masks) -> collective-safe.
__device__ __forceinline__ void blk_mma(float* d, unsigned act, unsigned lo,
                                        unsigned addr,
                                        unsigned a0, unsigned a1,
                                        unsigned a2, unsigned a3) {
    asm volatile(
        "{\n\t"
        ".reg .pred p, q;\n\t"
        ".reg .b32 bh, bl;\n\t"
        "setp.ne.u32 p, %4, 0;\n\t"
        "setp.ne.u32 q, %5, 0;\n\t"
        "@p ld.shared.v2.b32 {bh, bl}, [%6];\n\t"
        "@p mma.sync.aligned.m16n8k16.row.col.f32.f16.f16.f32 "
        "{%0,%1,%2,%3}, {%7,%8,%9,%10}, {bh,bh}, {%0,%1,%2,%3};\n\t"
        "@q mma.sync.aligned.m16n8k16.row.col.f32.f16.f16.f32 "
        "{%0,%1,%2,%3}, {%7,%8,%9,%10}, {bl,bl}, {%0,%1,%2,%3};\n\t"
        "}"
        : "+f"(d[0]), "+f"(d[1]), "+f"(d[2]), "+f"(d[3])
        : "r"(act), "r"(lo), "r"(addr),
          "r"(a0), "r"(a1), "r"(a2), "r"(a3));
}

// shared (floats): in1s[1152] | in2s[1152] | mask[16] | lomask[16] | sB (uint2)
#define IN1_OFF  0
#define IN2_OFF  1152
#define MASK_OFF 2304
#define LOM_OFF  2320
#define SB_OFF   2336                          // 2336*4 % 8 == 0
#define SMEM_FLOATS (SB_OFF + NBLK * 64)       // 2336 + 7744 = 10080 -> 40320 B

__global__ void __launch_bounds__(TPB, 3) tp_mma(
    const float* __restrict__ in1,
    const float* __restrict__ in2,
    float* __restrict__ out,
    int B)
{
    extern __shared__ float smem[];
    float*    in1s  = smem + IN1_OFF;
    float*    in2s  = smem + IN2_OFF;
    unsigned* smask = (unsigned*)(smem + MASK_OFF);
    unsigned* sloms = (unsigned*)(smem + LOM_OFF);
    uint2*    sB    = (uint2*)(smem + SB_OFF);

    const int tid  = threadIdx.x;
    const int base = blockIdx.x * ROWS;

    const int lim = B * 9 - base * 9;
    for (int idx = tid; idx < ROWS * 9; idx += TPB) {
        bool ok = idx < lim;
        in1s[idx] = ok ? in1[base * 9 + idx] : 0.f;
        in2s[idx] = ok ? in2[base * 9 + idx] : 0.f;
    }
    const int nslot = g_nslot;
    for (int idx = tid; idx < nslot * 32; idx += TPB) sB[idx] = g_blk[idx];
    if (tid < KT) { smask[tid] = g_mask[tid]; sloms[tid] = g_lomask[tid]; }
    __syncthreads();

    const int lane = tid & 31;
    const int warp = tid >> 5;
    const int g = lane >> 2;
    const int t = lane & 3;
    const int r0 = warp * 16 + g;
    const int r1 = r0 + 8;

    float acc[NT][4];
#pragma unroll
    for (int n = 0; n < NT; n++) {
        acc[n][0] = 0.f; acc[n][1] = 0.f; acc[n][2] = 0.f; acc[n][3] = 0.f;
    }

    const float* a0p = in1s + r0 * 9;
    const float* a1p = in1s + r1 * 9;
    const float* c0p = in2s + r0 * 9;
    const float* c1p = in2s + r1 * 9;

    // base shared address of this lane's B-frag slot 0
    unsigned addr0 = (unsigned)__cvta_generic_to_shared(sB + lane);
    unsigned slot_b = 0;    // advances 256 B per ACTIVE block (branchlessly)

#pragma unroll
    for (int kt = 0; kt < KT; kt++) {
        const int c0 = kt * 8 + 2 * t;
        const int c1 = c0 + 1;
        const int i0 = (c0 * 57) >> 9;  const int j0 = c0 - 9 * i0;
        const int i1 = (c1 * 57) >> 9;  const int j1 = c1 - 9 * i1;

        float p00 = a0p[i0] * c0p[j0];
        float p10 = a1p[i0] * c1p[j0];
        float p01 = a0p[i1] * c0p[j1];
        float p11 = a1p[i1] * c1p[j1];
        if (c0 >= NIJ) { p00 = 0.f; p10 = 0.f; }
        if (c1 >= NIJ) { p01 = 0.f; p11 = 0.f; }

        // single-instruction packs (F2FP)
        __half2 h0 = __floats2half2_rn(p00, p01);
        __half2 h1 = __floats2half2_rn(p10, p11);
        float2 f0 = __half22float2(h0);
        float2 f1 = __half22float2(h1);
        __half2 l0 = __floats2half2_rn(p00 - f0.x, p01 - f0.y);
        __half2 l1 = __floats2half2_rn(p10 - f1.x, p11 - f1.y);
        const unsigned ra0 = *(unsigned*)&h0;
        const unsigned ra1 = *(unsigned*)&h1;
        const unsigned ra2 = *(unsigned*)&l0;
        const unsigned ra3 = *(unsigned*)&l1;

        const unsigned m  = smask[kt];
        const unsigned ml = sloms[kt];
#pragma unroll
        for (int nt = 0; nt < NT; nt++) {
            const unsigned act = (m  >> nt) & 1u;
            const unsigned lo  = (ml >> nt) & 1u;
            blk_mma(acc[nt], act, lo, addr0 + slot_b, ra0, ra1, ra2, ra3);
            slot_b += act << 8;                  // 32 lanes * 8 B
        }
    }

    // direct scalar stores (324 B rows -> STG.32 only), both elements guarded
    const int row0 = base + r0;
    const int row1 = base + r1;
    const bool ok0 = row0 < B;
    const bool ok1 = row1 < B;
    float* o0 = out + row0 * NKOUT;
    float* o1 = out + row1 * NKOUT;
#pragma unroll
    for (int nt = 0; nt < NT; nt++) {
        const int c = nt * 8 + 2 * t;
        if (ok0) {
            if (c < NKOUT)     o0[c]     = acc[nt][0];
            if (c + 1 < NKOUT) o0[c + 1] = acc[nt][1];
        }
        if (ok1) {
            if (c < NKOUT)     o1[c]     = acc[nt][2];
            if (c + 1 < NKOUT) o1[c + 1] = acc[nt][3];
        }
    }
}

extern "C" void kernel_launch(void* const* d_in, const int* in_sizes, int n_in,
                              void* d_out, int out_size) {
    const float* in1 = (const float*)d_in[0];
    const float* in2 = (const float*)d_in[1];
    const float* cb  = (const float*)d_in[2];
    float* out = (float*)d_out;

    const int B = in_sizes[0] / 9;
    const int grid = (B + ROWS - 1) / ROWS;
    const size_t smem_bytes = SMEM_FLOATS * sizeof(float);   // 40,320 B

    cudaFuncSetAttribute(tp_mma, cudaFuncAttributeMaxDynamicSharedMemorySize,
                         (int)smem_bytes);

    prep_kernel<<<1, 128>>>(cb);
    tp_mma<<<grid, TPB, smem_bytes>>>(in1, in2, out, B);
}

// round 10
// speedup vs baseline: 3.3230x; 3.3230x over previous
#include <cuda_runtime.h>
#include <cstdint>

// out[b,k] = sum_ij in1[b,i]*in2[b,j]*cb[k,ij]
// R2 skeleton (per-thread outer product P in shared, chunked O staging,
// coalesced division-free flush) with two structural changes:
//  1. nnz metadata lives in __constant__ (LDC port, off the L1 crossbar),
//     copied from a prep-written __device__ staging struct via one
//     cudaMemcpyAsync D2D inside kernel_launch (graph-capturable).
//  2. k-loop fully unrolled with FIXED 2 float4 meta groups (4 nnz) per k —
//     immediate constant addresses, no branches, no rowptr. Rows with >4 nnz
//     spill to a global overflow list (phase-segmented, any-cb-correct).

#define NK     81
#define NIJ    81
#define TPB    160
#define STRIDE 161       // odd -> conflict-free columns and transpose
#define CHUNK  27
#define NPH    3

struct Tbl {
    float4 meta[NK][2];   // per k: {idx_bytes0,w0,idx_bytes1,w1} x2 = 4 nnz
    int    ovp[NPH + 1];  // overflow rowptr per phase
    int    pad[4];
};

__device__ Tbl    g_stage;
__device__ float4 g_ovf[NK * NIJ];   // {o_bytes, q_bytes, w, 0}
__constant__ Tbl  c_tbl;

__global__ void prep_kernel(const float* __restrict__ cb) {
    __shared__ int ocnt[NK];
    __shared__ int ooff[NK + 1];
    const int k = threadIdx.x;
    if (k < NK) {
        int c = 0;
        for (int ij = 0; ij < NIJ; ij++)
            if (cb[k * NIJ + ij] != 0.f) c++;
        ocnt[k] = (c > 4) ? (c - 4) : 0;
    }
    __syncthreads();
    if (k == 0) {
        int s = 0;
        for (int q = 0; q < NK; q++) { ooff[q] = s; s += ocnt[q]; }
        ooff[NK] = s;
        g_stage.ovp[0] = 0;
        g_stage.ovp[1] = ooff[1 * CHUNK];
        g_stage.ovp[2] = ooff[2 * CHUNK];
        g_stage.ovp[3] = s;              // entries are k-ascending -> phase-contiguous
    }
    __syncthreads();
    if (k < NK) {
        float id[4] = {0.f, 0.f, 0.f, 0.f};
        float w [4] = {0.f, 0.f, 0.f, 0.f};
        int n = 0;
        int o = ooff[k];
        const int kl = k % CHUNK;        // row index inside its phase chunk
        for (int ij = 0; ij < NIJ; ij++) {
            float v = cb[k * NIJ + ij];
            if (v != 0.f) {
                if (n < 4) { id[n] = __int_as_float(ij * STRIDE * 4); w[n] = v; n++; }
                else g_ovf[o++] = make_float4(__int_as_float(kl * STRIDE * 4),
                                              __int_as_float(ij * STRIDE * 4), v, 0.f);
            }
        }
        g_stage.meta[k][0] = make_float4(id[0], w[0], id[1], w[1]);
        g_stage.meta[k][1] = make_float4(id[2], w[2], id[3], w[3]);
    }
}

__global__ void __launch_bounds__(TPB, 3) tp_kernel(
    const float* __restrict__ in1,
    const float* __restrict__ in2,
    float* __restrict__ out,
    int B)
{
    extern __shared__ float smem[];
    float* P = smem;                       // NIJ * STRIDE floats
    float* O = smem + NIJ * STRIDE;        // CHUNK * STRIDE floats

    const int t = threadIdx.x;
    const int b = blockIdx.x * TPB + t;

    float a[9], c9[9];
    if (b < B) {
#pragma unroll
        for (int i = 0; i < 9; i++) a[i]  = __ldg(&in1[b * 9 + i]);
#pragma unroll
        for (int j = 0; j < 9; j++) c9[j] = __ldg(&in2[b * 9 + j]);
    } else {
#pragma unroll
        for (int i = 0; i < 9; i++) { a[i] = 0.f; c9[i] = 0.f; }
    }

    // outer product into own shared column (only this thread reads it -> no sync)
    char* Pb = (char*)P + t * 4;
#pragma unroll
    for (int i = 0; i < 9; i++)
#pragma unroll
        for (int j = 0; j < 9; j++)
            *(float*)(Pb + (i * 9 + j) * STRIDE * 4) = a[i] * c9[j];

    const int limit  = B * NK;                   // 84,934,656 < 2^31
    const int gbase0 = blockIdx.x * TPB * NK;
    char* Ob = (char*)O + t * 4;

#pragma unroll
    for (int ph = 0; ph < NPH; ph++) {
        // ---- contraction: fixed 4 nnz per k, immediate constant addresses ----
#pragma unroll
        for (int kq = 0; kq < CHUNK; kq++) {
            const float4 m0 = c_tbl.meta[ph * CHUNK + kq][0];
            const float4 m1 = c_tbl.meta[ph * CHUNK + kq][1];
            float s0 = m0.y * (*(const float*)(Pb + __float_as_int(m0.x)));
            float s1 = m0.w * (*(const float*)(Pb + __float_as_int(m0.z)));
            s0 = fmaf(m1.y, *(const float*)(Pb + __float_as_int(m1.x)), s0);
            s1 = fmaf(m1.w, *(const float*)(Pb + __float_as_int(m1.z)), s1);
            *(float*)(Ob + kq * STRIDE * 4) = s0 + s1;
        }
        // ---- rare overflow entries (rows with >4 nnz), own-column += ----
        {
            const int r1 = c_tbl.ovp[ph + 1];
#pragma unroll 1
            for (int r = c_tbl.ovp[ph]; r < r1; r++) {
                const float4 e = g_ovf[r];
                float* op = (float*)(Ob + __float_as_int(e.x));
                *op = fmaf(e.z, *(const float*)(Pb + __float_as_int(e.y)), *op);
            }
        }
        __syncthreads();   // flush reads other threads' O columns

        // ---- coalesced flush, division-free incremental indexing (R2-proven) ----
        {
            int bl = t / CHUNK;
            int kq = t - bl * CHUNK;
            int gi = bl * NK + kq;
            int si = kq * STRIDE + bl;
            const int gb = gbase0 + ph * CHUNK;
#pragma unroll
            for (int rr = 0; rr < CHUNK; rr++) {
                int g = gb + gi;
                if (g < limit) out[g] = O[si];
                kq += 25;                         // advance slot by TPB=160
                if (kq >= CHUNK) {
                    kq -= CHUNK;
                    gi += 5 * NK + 25 + (NK - CHUNK);             // 484
                    si += 25 * STRIDE + 5 - (CHUNK * STRIDE - 1); // -316
                } else {
                    gi += 5 * NK + 25;                            // 430
                    si += 25 * STRIDE + 5;                        // 4030
                }
            }
        }
        __syncthreads();   // next phase reuses O
    }
}

extern "C" void kernel_launch(void* const* d_in, const int* in_sizes, int n_in,
                              void* d_out, int out_size) {
    const float* in1 = (const float*)d_in[0];
    const float* in2 = (const float*)d_in[1];
    const float* cb  = (const float*)d_in[2];
    float* out = (float*)d_out;

    const int B = in_sizes[0] / 9;

    const size_t smem_bytes =
        (size_t)(NIJ * STRIDE) * sizeof(float) +     // P  52,164
        (size_t)(CHUNK * STRIDE) * sizeof(float);    // O  17,388  -> 69,552 B, 3 CTAs/SM

    cudaFuncSetAttribute(tp_kernel,
                         cudaFuncAttributeMaxDynamicSharedMemorySize,
                         (int)smem_bytes);

    prep_kernel<<<1, 96>>>(cb);

    // constant table <- staging (device-to-device, graph-capturable)
    void *dst = nullptr, *src = nullptr;
    cudaGetSymbolAddress(&dst, c_tbl);
    cudaGetSymbolAddress(&src, g_stage);
    cudaMemcpyAsync(dst, src, sizeof(Tbl), cudaMemcpyDeviceToDevice, 0);

    tp_kernel<<<(B + TPB - 1) / TPB, TPB, smem_bytes>>>(in1, in2, out, B);
}